// round 1
// baseline (speedup 1.0000x reference)
#include <cuda_runtime.h>
#include <cuda_bf16.h>
#include <math.h>

// ---------------- problem constants ----------------
#define BB   16
#define CC   192
#define LL   4096              // H*W = 64*64
#define MM   (BB*LL)           // 65536 rows
#define DI   384               // D_INNER
#define DS   16                // D_STATE
#define DTR  12                // DT_RANK
#define NX   (DTR + 2*DS)      // 44

// ---------------- scratch (device globals; no allocations) ----------------
__device__ float g_xn [ (size_t)MM * CC ];      // layernormed, (B*L, C)
__device__ float g_xz [ (size_t)MM * 2*DI ];    // xi | z, (B*L, 768)
__device__ float g_u  [ (size_t)MM * DI ];      // silu(conv(xi))
__device__ float g_dt [ (size_t)MM * DI ];
__device__ float g_B  [ (size_t)MM * DS ];
__device__ float g_C  [ (size_t)MM * DS ];
__device__ float g_yg [ (size_t)MM * DI ];      // gated y (GEMM3 input)
__device__ float g_yo [ (size_t)MM * CC ];      // GEMM3 output (B*L, C)

// ---------------- K1: layernorm over C + layout to (B,L,C) ----------------
__global__ void k_ln(const float* __restrict__ x, const float* __restrict__ g,
                     const float* __restrict__ bt) {
    __shared__ float s[CC][33];
    __shared__ float s_mu[32], s_rs[32];
    int b  = blockIdx.y;
    int p0 = blockIdx.x * 32;
    int tx = threadIdx.x;          // 0..31
    int ty = threadIdx.y;          // 0..7
    const float* xb = x + (size_t)b * CC * LL;
    for (int c = ty; c < CC; c += 8)
        s[c][tx] = xb[(size_t)c * LL + p0 + tx];
    __syncthreads();
    int tid = ty * 32 + tx;
    if (tid < 32) {
        float sum = 0.f, sq = 0.f;
        #pragma unroll 4
        for (int c = 0; c < CC; c++) { float v = s[c][tid]; sum += v; sq += v*v; }
        float mu  = sum * (1.f/CC);
        float var = sq  * (1.f/CC) - mu*mu;
        s_mu[tid] = mu;
        s_rs[tid] = rsqrtf(var + 1e-5f);
    }
    __syncthreads();
    float* xnb = g_xn + ((size_t)b * LL + p0) * CC;
    for (int idx = tid; idx < 32 * CC; idx += 256) {
        int p = idx / CC, c = idx % CC;
        xnb[(size_t)p * CC + c] = (s[c][p] - s_mu[p]) * s_rs[p] * g[c] + bt[c];
    }
}

// ---------------- K2: SGEMM 128x64x8, 256 threads, 8x4 per thread --------
// C[M,N] = A[M,K] @ B[K,N]  (all row-major; M%128==0, N%64==0, K%8==0)
__global__ void __launch_bounds__(256)
k_sgemm(const float* __restrict__ A, const float* __restrict__ Bm,
        float* __restrict__ C, int M, int N, int K) {
    __shared__ float As[8][128];
    __shared__ float Bs[8][64];
    int t  = threadIdx.x;
    int bm = blockIdx.y * 128;
    int bn = blockIdx.x * 64;
    int a_row = t >> 1, a_col = (t & 1) * 4;
    int b_row = (t & 127) >> 4, b_col = (t & 15) * 4;
    int ty = t >> 4, tx = t & 15;
    float acc[8][4] = {};
    for (int k0 = 0; k0 < K; k0 += 8) {
        float4 av = *(const float4*)(A + (size_t)(bm + a_row) * K + k0 + a_col);
        As[a_col+0][a_row] = av.x; As[a_col+1][a_row] = av.y;
        As[a_col+2][a_row] = av.z; As[a_col+3][a_row] = av.w;
        if (t < 128) {
            float4 bv = *(const float4*)(Bm + (size_t)(k0 + b_row) * N + bn + b_col);
            *(float4*)(&Bs[b_row][b_col]) = bv;
        }
        __syncthreads();
        #pragma unroll
        for (int k = 0; k < 8; k++) {
            float ra[8], rb[4];
            #pragma unroll
            for (int i = 0; i < 8; i++) ra[i] = As[k][ty*8+i];
            #pragma unroll
            for (int j = 0; j < 4; j++) rb[j] = Bs[k][tx*4+j];
            #pragma unroll
            for (int i = 0; i < 8; i++)
                #pragma unroll
                for (int j = 0; j < 4; j++)
                    acc[i][j] = fmaf(ra[i], rb[j], acc[i][j]);
        }
        __syncthreads();
    }
    float* Cp = C + (size_t)(bm + ty*8) * N + bn + tx*4;
    #pragma unroll
    for (int i = 0; i < 8; i++)
        *(float4*)(Cp + (size_t)i * N) =
            make_float4(acc[i][0], acc[i][1], acc[i][2], acc[i][3]);
}

// ---------------- K3: depthwise causal conv (k=4) + bias + silu ----------
__global__ void k_conv(const float* __restrict__ cw, const float* __restrict__ cb) {
    int idx = blockIdx.x * blockDim.x + threadIdx.x;     // over B*L*DI
    if (idx >= MM * DI) return;
    int d = idx % DI;
    int l = (idx / DI) % LL;
    int b = idx / (DI * LL);
    const float* xi = g_xz + ((size_t)b * LL) * (2*DI) + d;   // xi = first half
    float acc = cb[d];
    #pragma unroll
    for (int j = 0; j < 4; j++) {
        int ll = l - 3 + j;
        if (ll >= 0) acc = fmaf(cw[d*4 + j], xi[(size_t)ll * (2*DI)], acc);
    }
    g_u[idx] = acc / (1.f + __expf(-acc));               // silu
}

// ---------------- K4: xdbc = u@W_x ; dt = softplus(dt_r@W_dt + b_dt) -----
__global__ void __launch_bounds__(128)
k_xdbc(const float* __restrict__ Wx, const float* __restrict__ Wdt,
       const float* __restrict__ bdt) {
    __shared__ float su[DI];
    __shared__ float sx[NX];
    int m = blockIdx.x;
    int t = threadIdx.x;
    const float* ur = g_u + (size_t)m * DI;
    for (int i = t; i < DI; i += 128) su[i] = ur[i];
    __syncthreads();
    if (t < NX) {
        float acc = 0.f;
        #pragma unroll 4
        for (int k = 0; k < DI; k++) acc = fmaf(su[k], Wx[k*NX + t], acc);
        sx[t] = acc;
        if (t >= DTR && t < DTR + DS)  g_B[(size_t)m*DS + (t - DTR)]      = acc;
        if (t >= DTR + DS)             g_C[(size_t)m*DS + (t - DTR - DS)] = acc;
    }
    __syncthreads();
    for (int d = t; d < DI; d += 128) {
        float acc = bdt[d];
        #pragma unroll
        for (int r = 0; r < DTR; r++) acc = fmaf(sx[r], Wdt[r*DI + d], acc);
        g_dt[(size_t)m*DI + d] = (acc > 20.f) ? acc : log1pf(__expf(acc));
    }
}

// ---------------- K5: selective scan (lane-per-state) + gate fusion ------
__global__ void __launch_bounds__(128)
k_scan(const float* __restrict__ Alog, const float* __restrict__ Dp) {
    int gid = blockIdx.x * blockDim.x + threadIdx.x;
    int grp = gid >> 4;                  // channel index in [0, B*DI)
    int s   = threadIdx.x & 15;          // state lane
    if (grp >= BB * DI) return;
    int b = grp / DI, d = grp % DI;
    float A   = -__expf(Alog[d*DS + s]);
    float Dpd = Dp[d];
    const float* up  = g_u  + ((size_t)b * LL) * DI + d;
    const float* dtp = g_dt + ((size_t)b * LL) * DI + d;
    const float* Bp  = g_B  + ((size_t)b * LL) * DS + s;
    const float* Cp  = g_C  + ((size_t)b * LL) * DS + s;
    const float* zp  = g_xz + ((size_t)b * LL) * (2*DI) + DI + d;  // z half
    float*       yp  = g_yg + ((size_t)b * LL) * DI + d;
    float h = 0.f;
    for (int l = 0; l < LL; l++) {
        float ut  = up [(size_t)l * DI];
        float dtt = dtp[(size_t)l * DI];
        float Bv  = Bp [(size_t)l * DS];
        float Cv  = Cp [(size_t)l * DS];
        float dA  = __expf(dtt * A);
        h = fmaf(h, dA, dtt * ut * Bv);
        float pr = h * Cv;
        pr += __shfl_xor_sync(0xffffffffu, pr, 8, 16);
        pr += __shfl_xor_sync(0xffffffffu, pr, 4, 16);
        pr += __shfl_xor_sync(0xffffffffu, pr, 2, 16);
        pr += __shfl_xor_sync(0xffffffffu, pr, 1, 16);
        if (s == 0) {
            float y = pr + ut * Dpd;
            float z = zp[(size_t)l * (2*DI)];
            y *= z / (1.f + __expf(-z));
            yp[(size_t)l * DI] = y;
        }
    }
}

// ---------------- K6: transpose (B,L,C)->(B,C,L) + residual --------------
__global__ void k_trans(const float* __restrict__ x, float* __restrict__ out) {
    __shared__ float ts[32][33];
    int b  = blockIdx.z;
    int c0 = blockIdx.y * 32;
    int p0 = blockIdx.x * 32;
    int tx = threadIdx.x, ty = threadIdx.y;   // 32 x 8
    for (int i = ty; i < 32; i += 8)
        ts[i][tx] = g_yo[((size_t)b * LL + p0 + i) * CC + c0 + tx];  // [p][c]
    __syncthreads();
    for (int i = ty; i < 32; i += 8) {
        size_t o = ((size_t)b * CC + c0 + i) * LL + p0 + tx;
        out[o] = ts[tx][i] + x[o];
    }
}

// ---------------- launch ----------------
extern "C" void kernel_launch(void* const* d_in, const int* in_sizes, int n_in,
                              void* d_out, int out_size) {
    const float* x      = (const float*)d_in[0];
    const float* ln_g   = (const float*)d_in[1];
    const float* ln_b   = (const float*)d_in[2];
    const float* W_in   = (const float*)d_in[3];
    const float* conv_w = (const float*)d_in[4];
    const float* conv_b = (const float*)d_in[5];
    const float* W_x    = (const float*)d_in[6];
    const float* W_dt   = (const float*)d_in[7];
    const float* b_dt   = (const float*)d_in[8];
    const float* A_log  = (const float*)d_in[9];
    const float* Dp     = (const float*)d_in[10];
    const float* W_out  = (const float*)d_in[11];
    float* out = (float*)d_out;

    float *p_xn, *p_xz, *p_yg, *p_yo;
    cudaGetSymbolAddress((void**)&p_xn, g_xn);
    cudaGetSymbolAddress((void**)&p_xz, g_xz);
    cudaGetSymbolAddress((void**)&p_yg, g_yg);
    cudaGetSymbolAddress((void**)&p_yo, g_yo);

    // K1 layernorm
    {
        dim3 grid(LL/32, BB), blk(32, 8);
        k_ln<<<grid, blk>>>(x, ln_g, ln_b);
    }
    // GEMM1: xz = xn @ W_in   (65536x192 @ 192x768)
    {
        dim3 grid((2*DI)/64, MM/128);
        k_sgemm<<<grid, 256>>>(p_xn, W_in, p_xz, MM, 2*DI, CC);
    }
    // conv + silu
    {
        int n = MM * DI;
        k_conv<<<(n + 255)/256, 256>>>(conv_w, conv_b);
    }
    // xdbc + dt
    k_xdbc<<<MM, 128>>>(W_x, W_dt, b_dt);
    // scan + gating
    k_scan<<<(BB*DI*16)/128, 128>>>(A_log, Dp);
    // GEMM3: yo = yg @ W_out  (65536x384 @ 384x192)
    {
        dim3 grid(CC/64, MM/128);
        k_sgemm<<<grid, 256>>>(p_yg, W_out, p_yo, MM, CC, DI);
    }
    // transpose + residual
    {
        dim3 grid(LL/32, CC/32, BB), blk(32, 8);
        k_trans<<<grid, blk>>>(x, out);
    }
}

// round 3
// speedup vs baseline: 1.7718x; 1.7718x over previous
#include <cuda_runtime.h>
#include <cuda_bf16.h>
#include <math.h>

// ---------------- problem constants ----------------
#define BB   16
#define CC   192
#define LL   4096              // H*W
#define MM   (BB*LL)           // 65536 rows
#define DI   384               // D_INNER
#define DS   16                // D_STATE
#define DTR  12                // DT_RANK
#define NX   (DTR + 2*DS)      // 44
#define NC   16                // scan chunks
#define CL   (LL/NC)           // 256 per chunk

// ---------------- scratch ----------------
__device__ float g_xn  [ (size_t)MM * CC ];
__device__ float g_xz  [ (size_t)MM * 2*DI ];
__device__ float g_u   [ (size_t)MM * DI ];
__device__ float g_dt  [ (size_t)MM * DI ];
__device__ float g_xdbc[ (size_t)MM * NX ];      // dt_r | B | C
__device__ float g_yg  [ (size_t)MM * DI ];
__device__ float g_yo  [ (size_t)MM * CC ];
__device__ float g_P   [ (size_t)NC * BB * DI * DS ];   // chunk dA products
__device__ float g_hl  [ (size_t)NC * BB * DI * DS ];   // chunk local end state
__device__ float g_hin [ (size_t)NC * BB * DI * DS ];   // chunk initial state

// ---------------- K1: layernorm over C + layout to (B,L,C) ----------------
__global__ void k_ln(const float* __restrict__ x, const float* __restrict__ g,
                     const float* __restrict__ bt) {
    __shared__ float s[CC][33];
    __shared__ float s_mu[32], s_rs[32];
    int b  = blockIdx.y;
    int p0 = blockIdx.x * 32;
    int tx = threadIdx.x, ty = threadIdx.y;
    const float* xb = x + (size_t)b * CC * LL;
    for (int c = ty; c < CC; c += 8)
        s[c][tx] = xb[(size_t)c * LL + p0 + tx];
    __syncthreads();
    int tid = ty * 32 + tx;
    if (tid < 32) {
        float sum = 0.f, sq = 0.f;
        #pragma unroll 4
        for (int c = 0; c < CC; c++) { float v = s[c][tid]; sum += v; sq += v*v; }
        float mu  = sum * (1.f/CC);
        float var = sq  * (1.f/CC) - mu*mu;
        s_mu[tid] = mu;
        s_rs[tid] = rsqrtf(var + 1e-5f);
    }
    __syncthreads();
    float* xnb = g_xn + ((size_t)b * LL + p0) * CC;
    for (int idx = tid; idx < 32 * CC; idx += 256) {
        int p = idx / CC, c = idx % CC;
        xnb[(size_t)p * CC + c] = (s[c][p] - s_mu[p]) * s_rs[p] * g[c] + bt[c];
    }
}

// ---------------- K2: SGEMM 128x64x8 (exact multiples) --------------------
__global__ void __launch_bounds__(256)
k_sgemm(const float* __restrict__ A, const float* __restrict__ Bm,
        float* __restrict__ C, int M, int N, int K) {
    __shared__ float As[8][128];
    __shared__ float Bs[8][64];
    int t  = threadIdx.x;
    int bm = blockIdx.y * 128;
    int bn = blockIdx.x * 64;
    int a_row = t >> 1, a_col = (t & 1) * 4;
    int b_row = (t & 127) >> 4, b_col = (t & 15) * 4;
    int ty = t >> 4, tx = t & 15;
    float acc[8][4] = {};
    for (int k0 = 0; k0 < K; k0 += 8) {
        float4 av = *(const float4*)(A + (size_t)(bm + a_row) * K + k0 + a_col);
        As[a_col+0][a_row] = av.x; As[a_col+1][a_row] = av.y;
        As[a_col+2][a_row] = av.z; As[a_col+3][a_row] = av.w;
        if (t < 128) {
            float4 bv = *(const float4*)(Bm + (size_t)(k0 + b_row) * N + bn + b_col);
            *(float4*)(&Bs[b_row][b_col]) = bv;
        }
        __syncthreads();
        #pragma unroll
        for (int k = 0; k < 8; k++) {
            float ra[8], rb[4];
            #pragma unroll
            for (int i = 0; i < 8; i++) ra[i] = As[k][ty*8+i];
            #pragma unroll
            for (int j = 0; j < 4; j++) rb[j] = Bs[k][tx*4+j];
            #pragma unroll
            for (int i = 0; i < 8; i++)
                #pragma unroll
                for (int j = 0; j < 4; j++)
                    acc[i][j] = fmaf(ra[i], rb[j], acc[i][j]);
        }
        __syncthreads();
    }
    float* Cp = C + (size_t)(bm + ty*8) * N + bn + tx*4;
    #pragma unroll
    for (int i = 0; i < 8; i++)
        *(float4*)(Cp + (size_t)i * N) =
            make_float4(acc[i][0], acc[i][1], acc[i][2], acc[i][3]);
}

// ---------------- K2b: SGEMM with N guard (for N=44) ----------------------
__global__ void __launch_bounds__(256)
k_sgemm_ng(const float* __restrict__ A, const float* __restrict__ Bm,
           float* __restrict__ C, int M, int N, int K) {
    __shared__ float As[8][128];
    __shared__ float Bs[8][64];
    int t  = threadIdx.x;
    int bm = blockIdx.y * 128;
    int bn = blockIdx.x * 64;
    int a_row = t >> 1, a_col = (t & 1) * 4;
    int b_row = (t & 127) >> 4, b_col = (t & 15) * 4;
    int ty = t >> 4, tx = t & 15;
    float acc[8][4] = {};
    for (int k0 = 0; k0 < K; k0 += 8) {
        float4 av = *(const float4*)(A + (size_t)(bm + a_row) * K + k0 + a_col);
        As[a_col+0][a_row] = av.x; As[a_col+1][a_row] = av.y;
        As[a_col+2][a_row] = av.z; As[a_col+3][a_row] = av.w;
        if (t < 128) {
            #pragma unroll
            for (int j = 0; j < 4; j++) {
                int col = bn + b_col + j;
                Bs[b_row][b_col+j] = (col < N)
                    ? Bm[(size_t)(k0 + b_row) * N + col] : 0.f;
            }
        }
        __syncthreads();
        #pragma unroll
        for (int k = 0; k < 8; k++) {
            float ra[8], rb[4];
            #pragma unroll
            for (int i = 0; i < 8; i++) ra[i] = As[k][ty*8+i];
            #pragma unroll
            for (int j = 0; j < 4; j++) rb[j] = Bs[k][tx*4+j];
            #pragma unroll
            for (int i = 0; i < 8; i++)
                #pragma unroll
                for (int j = 0; j < 4; j++)
                    acc[i][j] = fmaf(ra[i], rb[j], acc[i][j]);
        }
        __syncthreads();
    }
    #pragma unroll
    for (int i = 0; i < 8; i++)
        #pragma unroll
        for (int j = 0; j < 4; j++) {
            int col = bn + tx*4 + j;
            if (col < N)
                C[(size_t)(bm + ty*8 + i) * N + col] = acc[i][j];
        }
}

// ---------------- K3: depthwise causal conv (k=4) + bias + silu ----------
__global__ void k_conv(const float* __restrict__ cw, const float* __restrict__ cb) {
    int idx = blockIdx.x * blockDim.x + threadIdx.x;
    if (idx >= MM * DI) return;
    int d = idx % DI;
    int l = (idx / DI) % LL;
    int b = idx / (DI * LL);
    const float* xi = g_xz + ((size_t)b * LL) * (2*DI) + d;
    float acc = cb[d];
    #pragma unroll
    for (int j = 0; j < 4; j++) {
        int ll = l - 3 + j;
        if (ll >= 0) acc = fmaf(cw[d*4 + j], xi[(size_t)ll * (2*DI)], acc);
    }
    g_u[idx] = acc / (1.f + __expf(-acc));
}

// ---------------- K4b: dt = softplus(dt_r @ W_dt + b_dt) ------------------
__global__ void __launch_bounds__(384)
k_dt(const float* __restrict__ Wdt, const float* __restrict__ bdt) {
    __shared__ float sdtr[64][DTR];
    int m0 = blockIdx.x * 64;
    int d  = threadIdx.x;          // 0..383
    for (int i = d; i < 64 * DTR; i += 384)
        sdtr[i / DTR][i % DTR] = g_xdbc[(size_t)(m0 + i / DTR) * NX + (i % DTR)];
    float w[DTR];
    #pragma unroll
    for (int k = 0; k < DTR; k++) w[k] = Wdt[k*DI + d];
    float bd = bdt[d];
    __syncthreads();
    for (int r = 0; r < 64; r++) {
        float acc = bd;
        #pragma unroll
        for (int k = 0; k < DTR; k++) acc = fmaf(sdtr[r][k], w[k], acc);
        g_dt[(size_t)(m0 + r) * DI + d] = (acc > 20.f) ? acc : log1pf(__expf(acc));
    }
}

// ---------------- K5a: scan pass1 — per-chunk P and local end state -------
__global__ void __launch_bounds__(128)
k_scan1(const float* __restrict__ Alog) {
    int gid = blockIdx.x * 128 + threadIdx.x;
    int grp = gid >> 4;                     // c*(BB*DI) + b*DI + d
    int s   = gid & 15;
    int c   = grp / (BB * DI);
    int bd  = grp % (BB * DI);
    int b = bd / DI, d = bd % DI;
    float A = -__expf(Alog[d*DS + s]);
    size_t m0 = (size_t)b * LL + (size_t)c * CL;
    const float* up  = g_u    + m0 * DI + d;
    const float* dtp = g_dt   + m0 * DI + d;
    const float* Bp  = g_xdbc + m0 * NX + DTR + s;
    float h = 0.f, P = 1.f;
    #pragma unroll 4
    for (int l = 0; l < CL; l++) {
        float ut  = up [(size_t)l * DI];
        float dtt = dtp[(size_t)l * DI];
        float Bv  = Bp [(size_t)l * NX];
        float dA  = __expf(dtt * A);
        P *= dA;
        h = fmaf(h, dA, dtt * ut * Bv);
    }
    g_P [gid] = P;
    g_hl[gid] = h;
}

// ---------------- K5b: serial combine over chunks (tiny) ------------------
__global__ void k_scan2() {
    int bds = blockIdx.x * blockDim.x + threadIdx.x;   // (b*DI+d)*DS+s
    if (bds >= BB * DI * DS) return;
    const int STRIDE = BB * DI * DS;
    float h = 0.f;
    #pragma unroll
    for (int c = 0; c < NC; c++) {
        g_hin[(size_t)c * STRIDE + bds] = h;
        h = fmaf(g_P[(size_t)c * STRIDE + bds], h, g_hl[(size_t)c * STRIDE + bds]);
    }
}

// ---------------- K5c: scan pass3 — full scan from known h_in, emit y -----
__global__ void __launch_bounds__(128)
k_scan3(const float* __restrict__ Alog, const float* __restrict__ Dp) {
    int gid = blockIdx.x * 128 + threadIdx.x;
    int grp = gid >> 4;
    int s   = gid & 15;
    int c   = grp / (BB * DI);
    int bd  = grp % (BB * DI);
    int b = bd / DI, d = bd % DI;
    float A   = -__expf(Alog[d*DS + s]);
    float Dpd = Dp[d];
    size_t m0 = (size_t)b * LL + (size_t)c * CL;
    const float* up  = g_u    + m0 * DI + d;
    const float* dtp = g_dt   + m0 * DI + d;
    const float* Bp  = g_xdbc + m0 * NX + DTR + s;
    const float* Cp  = g_xdbc + m0 * NX + DTR + DS + s;
    const float* zp  = g_xz   + m0 * (2*DI) + DI + d;
    float*       yp  = g_yg   + m0 * DI + d;
    float h = g_hin[gid];
    #pragma unroll 2
    for (int l = 0; l < CL; l++) {
        float ut  = up [(size_t)l * DI];
        float dtt = dtp[(size_t)l * DI];
        float Bv  = Bp [(size_t)l * NX];
        float Cv  = Cp [(size_t)l * NX];
        float dA  = __expf(dtt * A);
        h = fmaf(h, dA, dtt * ut * Bv);
        float pr = h * Cv;
        pr += __shfl_xor_sync(0xffffffffu, pr, 8, 16);
        pr += __shfl_xor_sync(0xffffffffu, pr, 4, 16);
        pr += __shfl_xor_sync(0xffffffffu, pr, 2, 16);
        pr += __shfl_xor_sync(0xffffffffu, pr, 1, 16);
        if (s == 0) {
            float y = pr + ut * Dpd;
            float z = zp[(size_t)l * (2*DI)];
            y *= z / (1.f + __expf(-z));
            yp[(size_t)l * DI] = y;
        }
    }
}

// ---------------- K6: transpose (B,L,C)->(B,C,L) + residual --------------
__global__ void k_trans(const float* __restrict__ x, float* __restrict__ out) {
    __shared__ float ts[32][33];
    int b  = blockIdx.z;
    int c0 = blockIdx.y * 32;
    int p0 = blockIdx.x * 32;
    int tx = threadIdx.x, ty = threadIdx.y;
    for (int i = ty; i < 32; i += 8)
        ts[i][tx] = g_yo[((size_t)b * LL + p0 + i) * CC + c0 + tx];
    __syncthreads();
    for (int i = ty; i < 32; i += 8) {
        size_t o = ((size_t)b * CC + c0 + i) * LL + p0 + tx;
        out[o] = ts[tx][i] + x[o];
    }
}

// ---------------- launch ----------------
extern "C" void kernel_launch(void* const* d_in, const int* in_sizes, int n_in,
                              void* d_out, int out_size) {
    const float* x      = (const float*)d_in[0];
    const float* ln_g   = (const float*)d_in[1];
    const float* ln_b   = (const float*)d_in[2];
    const float* W_in   = (const float*)d_in[3];
    const float* conv_w = (const float*)d_in[4];
    const float* conv_b = (const float*)d_in[5];
    const float* W_x    = (const float*)d_in[6];
    const float* W_dt   = (const float*)d_in[7];
    const float* b_dt   = (const float*)d_in[8];
    const float* A_log  = (const float*)d_in[9];
    const float* Dp     = (const float*)d_in[10];
    const float* W_out  = (const float*)d_in[11];
    float* out = (float*)d_out;

    float *p_xn, *p_xz, *p_u, *p_xdbc, *p_yg, *p_yo;
    cudaGetSymbolAddress((void**)&p_xn,   g_xn);
    cudaGetSymbolAddress((void**)&p_xz,   g_xz);
    cudaGetSymbolAddress((void**)&p_u,    g_u);
    cudaGetSymbolAddress((void**)&p_xdbc, g_xdbc);
    cudaGetSymbolAddress((void**)&p_yg,   g_yg);
    cudaGetSymbolAddress((void**)&p_yo,   g_yo);

    {   // layernorm
        dim3 grid(LL/32, BB), blk(32, 8);
        k_ln<<<grid, blk>>>(x, ln_g, ln_b);
    }
    {   // GEMM1: xz = xn @ W_in
        dim3 grid((2*DI)/64, MM/128);
        k_sgemm<<<grid, 256>>>(p_xn, W_in, p_xz, MM, 2*DI, CC);
    }
    {   // conv + silu
        int n = MM * DI;
        k_conv<<<(n + 255)/256, 256>>>(conv_w, conv_b);
    }
    {   // xdbc = u @ W_x   (N=44 guarded)
        dim3 grid(1, MM/128);
        k_sgemm_ng<<<grid, 256>>>(p_u, W_x, p_xdbc, MM, NX, DI);
    }
    // dt
    k_dt<<<MM/64, 384>>>(W_dt, b_dt);
    // chunked scan
    k_scan1<<<(NC*BB*DI*DS)/128, 128>>>(A_log);
    k_scan2<<<(BB*DI*DS + 255)/256, 256>>>();
    k_scan3<<<(NC*BB*DI*DS)/128, 128>>>(A_log, Dp);
    {   // GEMM3: yo = yg @ W_out
        dim3 grid(CC/64, MM/128);
        k_sgemm<<<grid, 256>>>(p_yg, W_out, p_yo, MM, CC, DI);
    }
    {   // transpose + residual
        dim3 grid(LL/32, CC/32, BB), blk(32, 8);
        k_trans<<<grid, blk>>>(x, out);
    }
}

// round 8
// speedup vs baseline: 1.9408x; 1.0954x over previous
#include <cuda_runtime.h>
#include <cuda_bf16.h>
#include <mma.h>
#include <math.h>
#include <stdint.h>

using namespace nvcuda;

// ---------------- problem constants ----------------
#define BB   16
#define CC   192
#define LL   4096              // H*W
#define MM   (BB*LL)           // 65536 rows
#define DI   384               // D_INNER
#define DS   16                // D_STATE
#define DTR  12                // DT_RANK
#define NX   44                // DTR + 2*DS (input W_x col count)
#define NXP  64                // padded row stride of g_xdbc
#define NC   32                // scan chunks
#define CL   (LL/NC)           // 128 per chunk

// ---------------- scratch ----------------
__device__ float g_xn  [ (size_t)MM * CC ];
__device__ float g_xz  [ (size_t)MM * 2*DI ];
__device__ float g_u   [ (size_t)MM * DI ];
__device__ float g_dt  [ (size_t)MM * DI ];
__device__ float g_xdbc[ (size_t)MM * NXP ];     // dt_r | B | C | pad
__device__ float g_yg  [ (size_t)MM * DI ];
__device__ float g_yo  [ (size_t)MM * CC ];
__device__ float g_P   [ (size_t)NC * BB * DI * DS ];
__device__ float g_hl  [ (size_t)NC * BB * DI * DS ];
__device__ float g_hin [ (size_t)NC * BB * DI * DS ];

// ---------------- K1: layernorm over C + layout to (B,L,C) ----------------
__global__ void k_ln(const float* __restrict__ x, const float* __restrict__ g,
                     const float* __restrict__ bt) {
    __shared__ float s[CC][33];
    __shared__ float s_mu[32], s_rs[32];
    int b  = blockIdx.y;
    int p0 = blockIdx.x * 32;
    int tx = threadIdx.x, ty = threadIdx.y;
    const float* xb = x + (size_t)b * CC * LL;
    for (int c = ty; c < CC; c += 8)
        s[c][tx] = xb[(size_t)c * LL + p0 + tx];
    __syncthreads();
    int tid = ty * 32 + tx;
    if (tid < 32) {
        float sum = 0.f, sq = 0.f;
        #pragma unroll 4
        for (int c = 0; c < CC; c++) { float v = s[c][tid]; sum += v; sq += v*v; }
        float mu  = sum * (1.f/CC);
        float var = sq  * (1.f/CC) - mu*mu;
        s_mu[tid] = mu;
        s_rs[tid] = rsqrtf(var + 1e-5f);
    }
    __syncthreads();
    float* xnb = g_xn + ((size_t)b * LL + p0) * CC;
    for (int idx = tid; idx < 32 * CC; idx += 256) {
        int p = idx / CC, c = idx % CC;
        xnb[(size_t)p * CC + c] = (s[c][p] - s_mu[p]) * s_rs[p] * g[c] + bt[c];
    }
}

// ---------------- K2: wmma tf32 GEMM, tile 128x64, k-step 32 --------------
// C[M, ldc] = A[M,K] @ B[K, ldb(=nvalid)] ; row-major everywhere.
// M%128==0, K%32==0. If NGUARD, B has nvalid (<64) columns and one col-block;
// C columns >= nvalid receive garbage (caller provides padded scratch).
template<bool NGUARD>
__global__ void __launch_bounds__(256)
k_wgemm(const float* __restrict__ A, const float* __restrict__ Bm,
        float* __restrict__ C, int M, int K, int nvalid, int ldc) {
    __shared__ float As[128][36];
    __shared__ float Bs[32][68];
    int t    = threadIdx.x;
    int bm   = blockIdx.y * 128, bn = blockIdx.x * 64;
    int warp = t >> 5;
    int wm   = warp >> 1, wn = warp & 1;        // 4x2 warp grid, 32x32 per warp

    wmma::fragment<wmma::accumulator, 16, 16, 8, float> acc[2][2];
    #pragma unroll
    for (int i = 0; i < 2; i++)
        #pragma unroll
        for (int j = 0; j < 2; j++)
            wmma::fill_fragment(acc[i][j], 0.0f);

    for (int k0 = 0; k0 < K; k0 += 32) {
        {   // A tile 128x32, float4 per thread x4
            int row = t >> 3, c4 = (t & 7) << 2;
            #pragma unroll
            for (int r = 0; r < 4; r++) {
                float4 v = *(const float4*)(A + (size_t)(bm + row + r*32) * K + k0 + c4);
                *(float4*)&As[row + r*32][c4] = v;
            }
        }
        if (!NGUARD) {  // B tile 32x64 vectorized (ldb == 64-multiple N)
            int row = t >> 4, c4 = (t & 15) << 2;
            #pragma unroll
            for (int r = 0; r < 2; r++) {
                float4 v = *(const float4*)(Bm + (size_t)(k0 + row + r*16) * nvalid + bn + c4);
                *(float4*)&Bs[row + r*16][c4] = v;
            }
        } else {        // guarded scalar fill, zero-pad cols >= nvalid
            #pragma unroll
            for (int r = 0; r < 8; r++) {
                int idx = r*256 + t;
                int row = idx >> 6, col = idx & 63;
                Bs[row][col] = (col < nvalid)
                    ? Bm[(size_t)(k0 + row) * nvalid + col] : 0.f;
            }
        }
        __syncthreads();
        #pragma unroll
        for (int kk = 0; kk < 32; kk += 8) {
            wmma::fragment<wmma::matrix_a, 16, 16, 8, wmma::precision::tf32, wmma::row_major> fa[2];
            wmma::fragment<wmma::matrix_b, 16, 16, 8, wmma::precision::tf32, wmma::row_major> fb[2];
            #pragma unroll
            for (int i = 0; i < 2; i++) {
                wmma::load_matrix_sync(fa[i], &As[wm*32 + i*16][kk], 36);
                #pragma unroll
                for (int e = 0; e < fa[i].num_elements; e++)
                    fa[i].x[e] = wmma::__float_to_tf32(fa[i].x[e]);
            }
            #pragma unroll
            for (int j = 0; j < 2; j++) {
                wmma::load_matrix_sync(fb[j], &Bs[kk][wn*32 + j*16], 68);
                #pragma unroll
                for (int e = 0; e < fb[j].num_elements; e++)
                    fb[j].x[e] = wmma::__float_to_tf32(fb[j].x[e]);
            }
            #pragma unroll
            for (int i = 0; i < 2; i++)
                #pragma unroll
                for (int j = 0; j < 2; j++)
                    wmma::mma_sync(acc[i][j], fa[i], fb[j], acc[i][j]);
        }
        __syncthreads();
    }
    #pragma unroll
    for (int i = 0; i < 2; i++)
        #pragma unroll
        for (int j = 0; j < 2; j++)
            wmma::store_matrix_sync(
                C + (size_t)(bm + wm*32 + i*16) * ldc + bn + wn*32 + j*16,
                acc[i][j], ldc, wmma::mem_row_major);
}

// ---------------- K3: depthwise causal conv (k=4) + bias + silu ----------
__global__ void k_conv(const float* __restrict__ cw, const float* __restrict__ cb) {
    int idx = blockIdx.x * blockDim.x + threadIdx.x;
    if (idx >= MM * DI) return;
    int d = idx % DI;
    int l = (idx / DI) % LL;
    int b = idx / (DI * LL);
    const float* xi = g_xz + ((size_t)b * LL) * (2*DI) + d;
    float acc = cb[d];
    #pragma unroll
    for (int j = 0; j < 4; j++) {
        int ll = l - 3 + j;
        if (ll >= 0) acc = fmaf(cw[d*4 + j], xi[(size_t)ll * (2*DI)], acc);
    }
    g_u[idx] = acc / (1.f + __expf(-acc));
}

// ---------------- K4: dt = softplus(dt_r @ W_dt + b_dt) -------------------
__global__ void __launch_bounds__(384)
k_dt(const float* __restrict__ Wdt, const float* __restrict__ bdt) {
    __shared__ float sdtr[64][DTR];
    int m0 = blockIdx.x * 64;
    int d  = threadIdx.x;
    for (int i = d; i < 64 * DTR; i += 384)
        sdtr[i / DTR][i % DTR] = g_xdbc[(size_t)(m0 + i / DTR) * NXP + (i % DTR)];
    float w[DTR];
    #pragma unroll
    for (int k = 0; k < DTR; k++) w[k] = Wdt[k*DI + d];
    float bd = bdt[d];
    __syncthreads();
    for (int r = 0; r < 64; r++) {
        float acc = bd;
        #pragma unroll
        for (int k = 0; k < DTR; k++) acc = fmaf(sdtr[r][k], w[k], acc);
        g_dt[(size_t)(m0 + r) * DI + d] = (acc > 20.f) ? acc : log1pf(__expf(acc));
    }
}

// ---------------- K5a: scan pass1 — per-chunk P and local end state -------
__global__ void __launch_bounds__(128)
k_scan1(const float* __restrict__ Alog) {
    int gid = blockIdx.x * 128 + threadIdx.x;
    int grp = gid >> 4;
    int s   = gid & 15;
    int c   = grp / (BB * DI);
    int bd  = grp % (BB * DI);
    int b = bd / DI, d = bd % DI;
    float A = -__expf(Alog[d*DS + s]);
    size_t m0 = (size_t)b * LL + (size_t)c * CL;
    const float* up  = g_u    + m0 * DI + d;
    const float* dtp = g_dt   + m0 * DI + d;
    const float* Bp  = g_xdbc + m0 * NXP + DTR + s;
    float h = 0.f, P = 1.f;
    #pragma unroll 4
    for (int l = 0; l < CL; l++) {
        float ut  = up [(size_t)l * DI];
        float dtt = dtp[(size_t)l * DI];
        float Bv  = Bp [(size_t)l * NXP];
        float dA  = __expf(dtt * A);
        P *= dA;
        h = fmaf(h, dA, dtt * ut * Bv);
    }
    g_P [gid] = P;
    g_hl[gid] = h;
}

// ---------------- K5b: serial combine over chunks -------------------------
__global__ void k_scan2() {
    int bds = blockIdx.x * blockDim.x + threadIdx.x;
    if (bds >= BB * DI * DS) return;
    const int STRIDE = BB * DI * DS;
    float h = 0.f;
    #pragma unroll
    for (int c = 0; c < NC; c++) {
        g_hin[(size_t)c * STRIDE + bds] = h;
        h = fmaf(g_P[(size_t)c * STRIDE + bds], h, g_hl[(size_t)c * STRIDE + bds]);
    }
}

// ---------------- K5c: scan pass3 — scan from h_in, emit gated y ----------
__global__ void __launch_bounds__(128)
k_scan3(const float* __restrict__ Alog, const float* __restrict__ Dp) {
    int gid = blockIdx.x * 128 + threadIdx.x;
    int grp = gid >> 4;
    int s   = gid & 15;
    int c   = grp / (BB * DI);
    int bd  = grp % (BB * DI);
    int b = bd / DI, d = bd % DI;
    float A   = -__expf(Alog[d*DS + s]);
    float Dpd = Dp[d];
    size_t m0 = (size_t)b * LL + (size_t)c * CL;
    const float* up  = g_u    + m0 * DI + d;
    const float* dtp = g_dt   + m0 * DI + d;
    const float* Bp  = g_xdbc + m0 * NXP + DTR + s;
    const float* Cp  = g_xdbc + m0 * NXP + DTR + DS + s;
    const float* zp  = g_xz   + m0 * (2*DI) + DI + d;
    float*       yp  = g_yg   + m0 * DI + d;
    float h = g_hin[gid];
    #pragma unroll 2
    for (int l = 0; l < CL; l++) {
        float ut  = up [(size_t)l * DI];
        float dtt = dtp[(size_t)l * DI];
        float Bv  = Bp [(size_t)l * NXP];
        float Cv  = Cp [(size_t)l * NXP];
        float dA  = __expf(dtt * A);
        h = fmaf(h, dA, dtt * ut * Bv);
        float pr = h * Cv;
        pr += __shfl_xor_sync(0xffffffffu, pr, 8, 16);
        pr += __shfl_xor_sync(0xffffffffu, pr, 4, 16);
        pr += __shfl_xor_sync(0xffffffffu, pr, 2, 16);
        pr += __shfl_xor_sync(0xffffffffu, pr, 1, 16);
        if (s == 0) {
            float y = pr + ut * Dpd;
            float z = zp[(size_t)l * (2*DI)];
            y *= z / (1.f + __expf(-z));
            yp[(size_t)l * DI] = y;
        }
    }
}

// ---------------- K6: transpose (B,L,C)->(B,C,L) + residual --------------
__global__ void k_trans(const float* __restrict__ x, float* __restrict__ out) {
    __shared__ float ts[32][33];
    int b  = blockIdx.z;
    int c0 = blockIdx.y * 32;
    int p0 = blockIdx.x * 32;
    int tx = threadIdx.x, ty = threadIdx.y;
    for (int i = ty; i < 32; i += 8)
        ts[i][tx] = g_yo[((size_t)b * LL + p0 + i) * CC + c0 + tx];
    __syncthreads();
    for (int i = ty; i < 32; i += 8) {
        size_t o = ((size_t)b * CC + c0 + i) * LL + p0 + tx;
        out[o] = ts[tx][i] + x[o];
    }
}

// ---------------- launch ----------------
extern "C" void kernel_launch(void* const* d_in, const int* in_sizes, int n_in,
                              void* d_out, int out_size) {
    const float* x      = (const float*)d_in[0];
    const float* ln_g   = (const float*)d_in[1];
    const float* ln_b   = (const float*)d_in[2];
    const float* W_in   = (const float*)d_in[3];
    const float* conv_w = (const float*)d_in[4];
    const float* conv_b = (const float*)d_in[5];
    const float* W_x    = (const float*)d_in[6];
    const float* W_dt   = (const float*)d_in[7];
    const float* b_dt   = (const float*)d_in[8];
    const float* A_log  = (const float*)d_in[9];
    const float* Dp     = (const float*)d_in[10];
    const float* W_out  = (const float*)d_in[11];
    float* out = (float*)d_out;

    float *p_xn, *p_xz, *p_u, *p_xdbc, *p_yg, *p_yo;
    cudaGetSymbolAddress((void**)&p_xn,   g_xn);
    cudaGetSymbolAddress((void**)&p_xz,   g_xz);
    cudaGetSymbolAddress((void**)&p_u,    g_u);
    cudaGetSymbolAddress((void**)&p_xdbc, g_xdbc);
    cudaGetSymbolAddress((void**)&p_yg,   g_yg);
    cudaGetSymbolAddress((void**)&p_yo,   g_yo);

    {   // layernorm
        dim3 grid(LL/32, BB), blk(32, 8);
        k_ln<<<grid, blk>>>(x, ln_g, ln_b);
    }
    {   // GEMM1: xz = xn @ W_in   (65536 x 768 x 192)
        dim3 grid((2*DI)/64, MM/128);
        k_wgemm<false><<<grid, 256>>>(p_xn, W_in, p_xz, MM, CC, 2*DI, 2*DI);
    }
    {   // conv + silu
        int n = MM * DI;
        k_conv<<<(n + 255)/256, 256>>>(conv_w, conv_b);
    }
    {   // xdbc = u @ W_x   (N=44 valid, stored with stride 64)
        dim3 grid(1, MM/128);
        k_wgemm<true><<<grid, 256>>>(p_u, W_x, p_xdbc, MM, DI, NX, NXP);
    }
    // dt
    k_dt<<<MM/64, 384>>>(W_dt, b_dt);
    // chunked scan
    k_scan1<<<(NC*BB*DI*DS)/128, 128>>>(A_log);
    k_scan2<<<(BB*DI*DS + 255)/256, 256>>>();
    k_scan3<<<(NC*BB*DI*DS)/128, 128>>>(A_log, Dp);
    {   // GEMM3: yo = yg @ W_out  (65536 x 192 x 384)
        dim3 grid(CC/64, MM/128);
        k_wgemm<false><<<grid, 256>>>(p_yg, W_out, p_yo, MM, DI, CC, CC);
    }
    {   // transpose + residual
        dim3 grid(LL/32, CC/32, BB), blk(32, 8);
        k_trans<<<grid, blk>>>(x, out);
    }
}

// round 12
// speedup vs baseline: 2.1843x; 1.1255x over previous
#include <cuda_runtime.h>
#include <cuda_bf16.h>
#include <mma.h>
#include <math.h>
#include <stdint.h>

using namespace nvcuda;

// ---------------- problem constants ----------------
#define BB   16
#define CC   192
#define LL   4096              // H*W
#define MM   (BB*LL)           // 65536 rows
#define DI   384               // D_INNER
#define DS   16                // D_STATE
#define DTR  12                // DT_RANK
#define NX   44                // DTR + 2*DS (W_x col count)
#define NXP  64                // padded row stride of g_xdbc
#define NC   32                // scan chunks
#define CL   (LL/NC)           // 128 per chunk

// ---------------- scratch ----------------
__device__ float g_xn  [ (size_t)MM * CC ];
__device__ float g_xz  [ (size_t)MM * 2*DI ];
__device__ float g_u   [ (size_t)MM * DI ];
__device__ float g_dt  [ (size_t)MM * DI ];
__device__ float g_xdbc[ (size_t)MM * NXP ];     // dt_r | B | C | pad
__device__ float g_yg  [ (size_t)MM * DI ];
__device__ float g_P   [ (size_t)NC * BB * DI * DS ];
__device__ float g_hl  [ (size_t)NC * BB * DI * DS ];
__device__ float g_hin [ (size_t)NC * BB * DI * DS ];

// ---------------- K1: layernorm over C + layout to (B,L,C) ----------------
__global__ void k_ln(const float* __restrict__ x, const float* __restrict__ g,
                     const float* __restrict__ bt) {
    __shared__ float s[CC][33];
    __shared__ float s_mu[32], s_rs[32];
    int b  = blockIdx.y;
    int p0 = blockIdx.x * 32;
    int tx = threadIdx.x, ty = threadIdx.y;
    const float* xb = x + (size_t)b * CC * LL;
    for (int c = ty; c < CC; c += 8)
        s[c][tx] = xb[(size_t)c * LL + p0 + tx];
    __syncthreads();
    int tid = ty * 32 + tx;
    if (tid < 32) {
        float sum = 0.f, sq = 0.f;
        #pragma unroll 4
        for (int c = 0; c < CC; c++) { float v = s[c][tid]; sum += v; sq += v*v; }
        float mu  = sum * (1.f/CC);
        float var = sq  * (1.f/CC) - mu*mu;
        s_mu[tid] = mu;
        s_rs[tid] = rsqrtf(var + 1e-5f);
    }
    __syncthreads();
    float* xnb = g_xn + ((size_t)b * LL + p0) * CC;
    for (int idx = tid; idx < 32 * CC; idx += 256) {
        int p = idx / CC, c = idx % CC;
        xnb[(size_t)p * CC + c] = (s[c][p] - s_mu[p]) * s_rs[p] * g[c] + bt[c];
    }
}

// ---------------- K2: bf16 wmma GEMM, tile 128x64, k-step 32 --------------
// C[M,*] = A[M,KK] @ B[KK,nvalid]; row-major. M == MM multiples of 128.
// NGUARD: single col-block, nvalid<64, zero-padded; C has row stride ldc.
// TROUT:  epilogue writes transposed (B,C,L) + residual: C[(b*CC + n)*LL + l],
//         Xres added elementwise (same layout).
template<int KK, bool NGUARD, bool TROUT>
__global__ void __launch_bounds__(256, 3)
k_bgemm(const float* __restrict__ A, const float* __restrict__ Bm,
        float* __restrict__ C, const float* __restrict__ Xres,
        int nvalid, int ldc) {
    __shared__ __align__(16) __nv_bfloat16 As[128][40];
    __shared__ __align__(16) __nv_bfloat16 Bs[32][72];
    int t    = threadIdx.x;
    int bm   = blockIdx.y * 128, bn = blockIdx.x * 64;
    int warp = t >> 5;
    int wm   = warp >> 1, wn = warp & 1;        // 4x2 warps, 32x32 each

    wmma::fragment<wmma::accumulator, 16, 16, 16, float> acc[2][2];
    #pragma unroll
    for (int i = 0; i < 2; i++)
        #pragma unroll
        for (int j = 0; j < 2; j++)
            wmma::fill_fragment(acc[i][j], 0.0f);

    for (int k0 = 0; k0 < KK; k0 += 32) {
        {   // A tile 128x32 -> bf16
            int row = t >> 3, c4 = (t & 7) << 2;
            #pragma unroll
            for (int r = 0; r < 4; r++) {
                float4 v = *(const float4*)(A + (size_t)(bm + row + r*32) * KK + k0 + c4);
                __nv_bfloat162 p0 = __floats2bfloat162_rn(v.x, v.y);
                __nv_bfloat162 p1 = __floats2bfloat162_rn(v.z, v.w);
                *(__nv_bfloat162*)&As[row + r*32][c4]     = p0;
                *(__nv_bfloat162*)&As[row + r*32][c4 + 2] = p1;
            }
        }
        if (!NGUARD) {  // B tile 32x64 -> bf16 (nvalid is row stride & >=64)
            int row = t >> 4, c4 = (t & 15) << 2;
            #pragma unroll
            for (int r = 0; r < 2; r++) {
                float4 v = *(const float4*)(Bm + (size_t)(k0 + row + r*16) * nvalid + bn + c4);
                __nv_bfloat162 p0 = __floats2bfloat162_rn(v.x, v.y);
                __nv_bfloat162 p1 = __floats2bfloat162_rn(v.z, v.w);
                *(__nv_bfloat162*)&Bs[row + r*16][c4]     = p0;
                *(__nv_bfloat162*)&Bs[row + r*16][c4 + 2] = p1;
            }
        } else {        // guarded scalar fill, zero-pad
            #pragma unroll
            for (int r = 0; r < 8; r++) {
                int idx = r*256 + t;
                int row = idx >> 6, col = idx & 63;
                float v = (col < nvalid) ? Bm[(size_t)(k0 + row) * nvalid + col] : 0.f;
                Bs[row][col] = __float2bfloat16_rn(v);
            }
        }
        __syncthreads();
        #pragma unroll
        for (int kk = 0; kk < 32; kk += 16) {
            wmma::fragment<wmma::matrix_a, 16, 16, 16, __nv_bfloat16, wmma::row_major> fa[2];
            wmma::fragment<wmma::matrix_b, 16, 16, 16, __nv_bfloat16, wmma::row_major> fb[2];
            #pragma unroll
            for (int i = 0; i < 2; i++)
                wmma::load_matrix_sync(fa[i], &As[wm*32 + i*16][kk], 40);
            #pragma unroll
            for (int j = 0; j < 2; j++)
                wmma::load_matrix_sync(fb[j], &Bs[kk][wn*32 + j*16], 72);
            #pragma unroll
            for (int i = 0; i < 2; i++)
                #pragma unroll
                for (int j = 0; j < 2; j++)
                    wmma::mma_sync(acc[i][j], fa[i], fb[j], acc[i][j]);
        }
        __syncthreads();
    }

    if (!TROUT) {
        #pragma unroll
        for (int i = 0; i < 2; i++)
            #pragma unroll
            for (int j = 0; j < 2; j++)
                wmma::store_matrix_sync(
                    C + (size_t)(bm + wm*32 + i*16) * ldc + bn + wn*32 + j*16,
                    acc[i][j], ldc, wmma::mem_row_major);
    } else {
        // out[(b*CC + n)*LL + l] = acc + x[same];  n = channel, l = position
        int b  = bm >> 12;          // bm / 4096
        int l0 = bm & 4095;
        #pragma unroll
        for (int i = 0; i < 2; i++)
            #pragma unroll
            for (int j = 0; j < 2; j++) {
                int n = bn + wn*32 + j*16;
                int l = l0 + wm*32 + i*16;
                size_t off = ((size_t)b * CC + n) * LL + l;
                wmma::fragment<wmma::accumulator, 16, 16, 16, float> xf;
                wmma::load_matrix_sync(xf, Xres + off, LL, wmma::mem_col_major);
                #pragma unroll
                for (int e = 0; e < xf.num_elements; e++)
                    acc[i][j].x[e] += xf.x[e];
                wmma::store_matrix_sync(C + off, acc[i][j], LL, wmma::mem_col_major);
            }
    }
}

// ---------------- K3: depthwise causal conv (k=4) + bias + silu ----------
__global__ void k_conv(const float* __restrict__ cw, const float* __restrict__ cb) {
    int idx = blockIdx.x * blockDim.x + threadIdx.x;
    if (idx >= MM * DI) return;
    int d = idx % DI;
    int l = (idx / DI) % LL;
    int b = idx / (DI * LL);
    const float* xi = g_xz + ((size_t)b * LL) * (2*DI) + d;
    float acc = cb[d];
    #pragma unroll
    for (int j = 0; j < 4; j++) {
        int ll = l - 3 + j;
        if (ll >= 0) acc = fmaf(cw[d*4 + j], xi[(size_t)ll * (2*DI)], acc);
    }
    g_u[idx] = acc / (1.f + __expf(-acc));
}

// ---------------- K4: dt = softplus(dt_r @ W_dt + b_dt) -------------------
__global__ void __launch_bounds__(384)
k_dt(const float* __restrict__ Wdt, const float* __restrict__ bdt) {
    __shared__ float sdtr[64][DTR];
    int m0 = blockIdx.x * 64;
    int d  = threadIdx.x;
    for (int i = d; i < 64 * DTR; i += 384)
        sdtr[i / DTR][i % DTR] = g_xdbc[(size_t)(m0 + i / DTR) * NXP + (i % DTR)];
    float w[DTR];
    #pragma unroll
    for (int k = 0; k < DTR; k++) w[k] = Wdt[k*DI + d];
    float bd = bdt[d];
    __syncthreads();
    for (int r = 0; r < 64; r++) {
        float acc = bd;
        #pragma unroll
        for (int k = 0; k < DTR; k++) acc = fmaf(sdtr[r][k], w[k], acc);
        g_dt[(size_t)(m0 + r) * DI + d] = (acc > 20.f) ? acc : log1pf(__expf(acc));
    }
}

// ---------------- K5a: scan pass1 — per-chunk P and local end state -------
__global__ void __launch_bounds__(128)
k_scan1(const float* __restrict__ Alog) {
    int gid = blockIdx.x * 128 + threadIdx.x;
    int grp = gid >> 4;
    int s   = gid & 15;
    int c   = grp / (BB * DI);
    int bd  = grp % (BB * DI);
    int b = bd / DI, d = bd % DI;
    float A = -__expf(Alog[d*DS + s]);
    size_t m0 = (size_t)b * LL + (size_t)c * CL;
    const float* up  = g_u    + m0 * DI + d;
    const float* dtp = g_dt   + m0 * DI + d;
    const float* Bp  = g_xdbc + m0 * NXP + DTR + s;
    float h = 0.f, P = 1.f;
    #pragma unroll 4
    for (int l = 0; l < CL; l++) {
        float ut  = up [(size_t)l * DI];
        float dtt = dtp[(size_t)l * DI];
        float Bv  = Bp [(size_t)l * NXP];
        float dA  = __expf(dtt * A);
        P *= dA;
        h = fmaf(h, dA, dtt * ut * Bv);
    }
    g_P [gid] = P;
    g_hl[gid] = h;
}

// ---------------- K5b: serial combine over chunks -------------------------
__global__ void k_scan2() {
    int bds = blockIdx.x * blockDim.x + threadIdx.x;
    if (bds >= BB * DI * DS) return;
    const int STRIDE = BB * DI * DS;
    float h = 0.f;
    #pragma unroll
    for (int c = 0; c < NC; c++) {
        g_hin[(size_t)c * STRIDE + bds] = h;
        h = fmaf(g_P[(size_t)c * STRIDE + bds], h, g_hl[(size_t)c * STRIDE + bds]);
    }
}

// ---------------- K5c: scan pass3 — scan from h_in, emit gated y ----------
__global__ void __launch_bounds__(128)
k_scan3(const float* __restrict__ Alog, const float* __restrict__ Dp) {
    int gid = blockIdx.x * 128 + threadIdx.x;
    int grp = gid >> 4;
    int s   = gid & 15;
    int c   = grp / (BB * DI);
    int bd  = grp % (BB * DI);
    int b = bd / DI, d = bd % DI;
    float A   = -__expf(Alog[d*DS + s]);
    float Dpd = Dp[d];
    size_t m0 = (size_t)b * LL + (size_t)c * CL;
    const float* up  = g_u    + m0 * DI + d;
    const float* dtp = g_dt   + m0 * DI + d;
    const float* Bp  = g_xdbc + m0 * NXP + DTR + s;
    const float* Cp  = g_xdbc + m0 * NXP + DTR + DS + s;
    const float* zp  = g_xz   + m0 * (2*DI) + DI + d;
    float*       yp  = g_yg   + m0 * DI + d;
    float h = g_hin[gid];
    #pragma unroll 2
    for (int l = 0; l < CL; l++) {
        float ut  = up [(size_t)l * DI];
        float dtt = dtp[(size_t)l * DI];
        float Bv  = Bp [(size_t)l * NXP];
        float Cv  = Cp [(size_t)l * NXP];
        float dA  = __expf(dtt * A);
        h = fmaf(h, dA, dtt * ut * Bv);
        float pr = h * Cv;
        pr += __shfl_xor_sync(0xffffffffu, pr, 8, 16);
        pr += __shfl_xor_sync(0xffffffffu, pr, 4, 16);
        pr += __shfl_xor_sync(0xffffffffu, pr, 2, 16);
        pr += __shfl_xor_sync(0xffffffffu, pr, 1, 16);
        if (s == 0) {
            float y = pr + ut * Dpd;
            float z = zp[(size_t)l * (2*DI)];
            y *= z / (1.f + __expf(-z));
            yp[(size_t)l * DI] = y;
        }
    }
}

// ---------------- launch ----------------
extern "C" void kernel_launch(void* const* d_in, const int* in_sizes, int n_in,
                              void* d_out, int out_size) {
    const float* x      = (const float*)d_in[0];
    const float* ln_g   = (const float*)d_in[1];
    const float* ln_b   = (const float*)d_in[2];
    const float* W_in   = (const float*)d_in[3];
    const float* conv_w = (const float*)d_in[4];
    const float* conv_b = (const float*)d_in[5];
    const float* W_x    = (const float*)d_in[6];
    const float* W_dt   = (const float*)d_in[7];
    const float* b_dt   = (const float*)d_in[8];
    const float* A_log  = (const float*)d_in[9];
    const float* Dp     = (const float*)d_in[10];
    const float* W_out  = (const float*)d_in[11];
    float* out = (float*)d_out;

    float *p_xn, *p_xz, *p_u, *p_xdbc, *p_yg;
    cudaGetSymbolAddress((void**)&p_xn,   g_xn);
    cudaGetSymbolAddress((void**)&p_xz,   g_xz);
    cudaGetSymbolAddress((void**)&p_u,    g_u);
    cudaGetSymbolAddress((void**)&p_xdbc, g_xdbc);
    cudaGetSymbolAddress((void**)&p_yg,   g_yg);

    {   // layernorm
        dim3 grid(LL/32, BB), blk(32, 8);
        k_ln<<<grid, blk>>>(x, ln_g, ln_b);
    }
    {   // GEMM1: xz = xn @ W_in   (65536 x 768 x 192)
        dim3 grid((2*DI)/64, MM/128);
        k_bgemm<CC, false, false><<<grid, 256>>>(p_xn, W_in, p_xz, nullptr, 2*DI, 2*DI);
    }
    {   // conv + silu
        int n = MM * DI;
        k_conv<<<(n + 255)/256, 256>>>(conv_w, conv_b);
    }
    {   // xdbc = u @ W_x   (N=44 valid, stored stride 64)
        dim3 grid(1, MM/128);
        k_bgemm<DI, true, false><<<grid, 256>>>(p_u, W_x, p_xdbc, nullptr, NX, NXP);
    }
    // dt
    k_dt<<<MM/64, 384>>>(W_dt, b_dt);
    // chunked scan
    k_scan1<<<(NC*BB*DI*DS)/128, 128>>>(A_log);
    k_scan2<<<(BB*DI*DS + 255)/256, 256>>>();
    k_scan3<<<(NC*BB*DI*DS)/128, 128>>>(A_log, Dp);
    {   // GEMM3 fused transpose+residual: out = (yg @ W_out)^T + x
        dim3 grid(CC/64, MM/128);
        k_bgemm<DI, false, true><<<grid, 256>>>(p_yg, W_out, out, x, CC, 0);
    }
}

// round 13
// speedup vs baseline: 2.5935x; 1.1873x over previous
#include <cuda_runtime.h>
#include <cuda_bf16.h>
#include <mma.h>
#include <math.h>
#include <stdint.h>

using namespace nvcuda;

// ---------------- problem constants ----------------
#define BB   16
#define CC   192
#define LL   4096              // H*W
#define MM   (BB*LL)           // 65536 rows
#define DI   384               // D_INNER
#define DS   16                // D_STATE
#define DTR  12                // DT_RANK
#define NX   44                // DTR + 2*DS (W_x col count)
#define NXP  64                // padded row stride of g_xdbc
#define NC   32                // scan chunks
#define CL   (LL/NC)           // 128 per chunk

// ---------------- scratch ----------------
__device__ __nv_bfloat16 g_xn [ (size_t)MM * CC ];   // LN out (bf16, GEMM1 A)
__device__ float         g_xz [ (size_t)MM * 2*DI ]; // xi | z (fp32)
__device__ float         g_u  [ (size_t)MM * DI ];   // fp32 (scan)
__device__ __nv_bfloat16 g_ub [ (size_t)MM * DI ];   // bf16(u) (xdbc GEMM A)
__device__ float         g_dt [ (size_t)MM * DI ];
__device__ float         g_xdbc[ (size_t)MM * NXP ]; // dt_r | B | C | pad
__device__ __nv_bfloat16 g_yg [ (size_t)MM * DI ];   // gated y (bf16, GEMM3 A)
__device__ float g_P  [ (size_t)NC * BB * DI * DS ];
__device__ float g_hl [ (size_t)NC * BB * DI * DS ];
__device__ float g_hin[ (size_t)NC * BB * DI * DS ];

// ---------------- cp.async helpers ----------------
__device__ __forceinline__ void cp16(void* s, const void* g) {
    uint32_t sa = (uint32_t)__cvta_generic_to_shared(s);
    asm volatile("cp.async.cg.shared.global [%0], [%1], 16;\n" :: "r"(sa), "l"(g));
}

// ---------------- K1: layernorm over C + layout to (B,L,C) bf16 -----------
__global__ void k_ln(const float* __restrict__ x, const float* __restrict__ g,
                     const float* __restrict__ bt) {
    __shared__ float s[CC][33];
    __shared__ float s_mu[32], s_rs[32];
    int b  = blockIdx.y;
    int p0 = blockIdx.x * 32;
    int tx = threadIdx.x, ty = threadIdx.y;
    const float* xb = x + (size_t)b * CC * LL;
    for (int c = ty; c < CC; c += 8)
        s[c][tx] = xb[(size_t)c * LL + p0 + tx];
    __syncthreads();
    int tid = ty * 32 + tx;
    if (tid < 32) {
        float sum = 0.f, sq = 0.f;
        #pragma unroll 4
        for (int c = 0; c < CC; c++) { float v = s[c][tid]; sum += v; sq += v*v; }
        float mu  = sum * (1.f/CC);
        float var = sq  * (1.f/CC) - mu*mu;
        s_mu[tid] = mu;
        s_rs[tid] = rsqrtf(var + 1e-5f);
    }
    __syncthreads();
    __nv_bfloat16* xnb = g_xn + ((size_t)b * LL + p0) * CC;
    for (int idx = tid; idx < 32 * CC; idx += 256) {
        int p = idx / CC, c = idx % CC;
        float v = (s[c][p] - s_mu[p]) * s_rs[p] * g[c] + bt[c];
        xnb[(size_t)p * CC + c] = __float2bfloat16_rn(v);
    }
}

// ---------------- K2: bf16 wmma GEMM, cp.async dbl-buffered A -------------
// C[M,*] = A[M,KK](bf16) @ B[KK,nvalid](fp32); row-major. KK%32==0.
// NGUARD: single col-block, nvalid<64 zero-padded, C row stride ldc.
// TROUT:  out[(b*CC+n)*LL+l] = acc + Xres[same] (transposed epilogue).
template<int KK, bool NGUARD, bool TROUT>
__global__ void __launch_bounds__(256)
k_bgemm16(const __nv_bfloat16* __restrict__ A, const float* __restrict__ Bm,
          float* __restrict__ C, const float* __restrict__ Xres,
          int nvalid, int ldc) {
    __shared__ __align__(16) __nv_bfloat16 As[2][128][40];
    __shared__ __align__(16) __nv_bfloat16 Bs[32][72];
    const int t    = threadIdx.x;
    const int bm   = blockIdx.y * 128, bn = blockIdx.x * 64;
    const int warp = t >> 5;
    const int wm   = warp >> 1, wn = warp & 1;       // 4x2 warps, 32x32 each

    wmma::fragment<wmma::accumulator, 16, 16, 16, float> acc[2][2];
    #pragma unroll
    for (int i = 0; i < 2; i++)
        #pragma unroll
        for (int j = 0; j < 2; j++)
            wmma::fill_fragment(acc[i][j], 0.0f);

    // issue A tile 0 (128x32 bf16 = 512 16B chunks, 2 per thread)
    #pragma unroll
    for (int r = 0; r < 2; r++) {
        int c = t + r*256, row = c >> 2, cc = (c & 3) << 3;
        cp16(&As[0][row][cc], A + (size_t)(bm + row) * KK + cc);
    }
    asm volatile("cp.async.commit_group;\n" ::: "memory");

    const int nk = KK / 32;
    #pragma unroll
    for (int i = 0; i < nk; i++) {
        int buf = i & 1;
        if (i + 1 < nk) {   // prefetch next A tile
            #pragma unroll
            for (int r = 0; r < 2; r++) {
                int c = t + r*256, row = c >> 2, cc = (c & 3) << 3;
                cp16(&As[buf^1][row][cc],
                     A + (size_t)(bm + row) * KK + (i+1)*32 + cc);
            }
            asm volatile("cp.async.commit_group;\n" ::: "memory");
        }
        // stage B tile i (32 x 64), fp32 -> bf16
        if (!NGUARD) {
            int row = t >> 4, c4 = (t & 15) << 2;
            #pragma unroll
            for (int r2 = 0; r2 < 2; r2++) {
                float4 v = *(const float4*)(Bm + (size_t)(i*32 + row + r2*16) * nvalid + bn + c4);
                *(__nv_bfloat162*)&Bs[row + r2*16][c4]     = __floats2bfloat162_rn(v.x, v.y);
                *(__nv_bfloat162*)&Bs[row + r2*16][c4 + 2] = __floats2bfloat162_rn(v.z, v.w);
            }
        } else {
            #pragma unroll
            for (int r2 = 0; r2 < 8; r2++) {
                int idx = r2*256 + t, row = idx >> 6, col = idx & 63;
                float v = (col < nvalid) ? Bm[(size_t)(i*32 + row) * nvalid + col] : 0.f;
                Bs[row][col] = __float2bfloat16_rn(v);
            }
        }
        if (i + 1 < nk) asm volatile("cp.async.wait_group 1;\n" ::: "memory");
        else            asm volatile("cp.async.wait_group 0;\n" ::: "memory");
        __syncthreads();
        #pragma unroll
        for (int kk = 0; kk < 32; kk += 16) {
            wmma::fragment<wmma::matrix_a, 16, 16, 16, __nv_bfloat16, wmma::row_major> fa[2];
            wmma::fragment<wmma::matrix_b, 16, 16, 16, __nv_bfloat16, wmma::row_major> fb[2];
            #pragma unroll
            for (int ii = 0; ii < 2; ii++)
                wmma::load_matrix_sync(fa[ii], &As[buf][wm*32 + ii*16][kk], 40);
            #pragma unroll
            for (int j = 0; j < 2; j++)
                wmma::load_matrix_sync(fb[j], &Bs[kk][wn*32 + j*16], 72);
            #pragma unroll
            for (int ii = 0; ii < 2; ii++)
                #pragma unroll
                for (int j = 0; j < 2; j++)
                    wmma::mma_sync(acc[ii][j], fa[ii], fb[j], acc[ii][j]);
        }
        __syncthreads();
    }

    if (!TROUT) {
        #pragma unroll
        for (int i = 0; i < 2; i++)
            #pragma unroll
            for (int j = 0; j < 2; j++)
                wmma::store_matrix_sync(
                    C + (size_t)(bm + wm*32 + i*16) * ldc + bn + wn*32 + j*16,
                    acc[i][j], ldc, wmma::mem_row_major);
    } else {
        int b  = bm >> 12;
        int l0 = bm & 4095;
        #pragma unroll
        for (int i = 0; i < 2; i++)
            #pragma unroll
            for (int j = 0; j < 2; j++) {
                int n = bn + wn*32 + j*16;
                int l = l0 + wm*32 + i*16;
                size_t off = ((size_t)b * CC + n) * LL + l;
                wmma::fragment<wmma::accumulator, 16, 16, 16, float> xf;
                wmma::load_matrix_sync(xf, Xres + off, LL, wmma::mem_col_major);
                #pragma unroll
                for (int e = 0; e < xf.num_elements; e++)
                    acc[i][j].x[e] += xf.x[e];
                wmma::store_matrix_sync(C + off, acc[i][j], LL, wmma::mem_col_major);
            }
    }
}

// ---------------- K3: depthwise causal conv + bias + silu (u fp32+bf16) --
__global__ void k_conv(const float* __restrict__ cw, const float* __restrict__ cb) {
    int idx = blockIdx.x * blockDim.x + threadIdx.x;
    if (idx >= MM * DI) return;
    int d = idx % DI;
    int l = (idx / DI) % LL;
    int b = idx / (DI * LL);
    const float* xi = g_xz + ((size_t)b * LL) * (2*DI) + d;
    float acc = cb[d];
    #pragma unroll
    for (int j = 0; j < 4; j++) {
        int ll = l - 3 + j;
        if (ll >= 0) acc = fmaf(cw[d*4 + j], xi[(size_t)ll * (2*DI)], acc);
    }
    float u = acc / (1.f + __expf(-acc));
    g_u [idx] = u;
    g_ub[idx] = __float2bfloat16_rn(u);
}

// ---------------- K4: dt = softplus(dt_r @ W_dt + b_dt) -------------------
__global__ void __launch_bounds__(384)
k_dt(const float* __restrict__ Wdt, const float* __restrict__ bdt) {
    __shared__ float sdtr[64][DTR];
    int m0 = blockIdx.x * 64;
    int d  = threadIdx.x;
    for (int i = d; i < 64 * DTR; i += 384)
        sdtr[i / DTR][i % DTR] = g_xdbc[(size_t)(m0 + i / DTR) * NXP + (i % DTR)];
    float w[DTR];
    #pragma unroll
    for (int k = 0; k < DTR; k++) w[k] = Wdt[k*DI + d];
    float bd = bdt[d];
    __syncthreads();
    for (int r = 0; r < 64; r++) {
        float acc = bd;
        #pragma unroll
        for (int k = 0; k < DTR; k++) acc = fmaf(sdtr[r][k], w[k], acc);
        g_dt[(size_t)(m0 + r) * DI + d] = (acc > 20.f) ? acc : log1pf(__expf(acc));
    }
}

// ---------------- K5a: scan pass1 — per-chunk P and local end state -------
__global__ void __launch_bounds__(128)
k_scan1(const float* __restrict__ Alog) {
    int gid = blockIdx.x * 128 + threadIdx.x;
    int grp = gid >> 4;
    int s   = gid & 15;
    int c   = grp / (BB * DI);
    int bd  = grp % (BB * DI);
    int b = bd / DI, d = bd % DI;
    float A = -__expf(Alog[d*DS + s]);
    size_t m0 = (size_t)b * LL + (size_t)c * CL;
    const float* up  = g_u    + m0 * DI + d;
    const float* dtp = g_dt   + m0 * DI + d;
    const float* Bp  = g_xdbc + m0 * NXP + DTR + s;
    float h = 0.f, P = 1.f;
    #pragma unroll 4
    for (int l = 0; l < CL; l++) {
        float ut  = up [(size_t)l * DI];
        float dtt = dtp[(size_t)l * DI];
        float Bv  = Bp [(size_t)l * NXP];
        float dA  = __expf(dtt * A);
        P *= dA;
        h = fmaf(h, dA, dtt * ut * Bv);
    }
    g_P [gid] = P;
    g_hl[gid] = h;
}

// ---------------- K5b: serial combine over chunks -------------------------
__global__ void k_scan2() {
    int bds = blockIdx.x * blockDim.x + threadIdx.x;
    if (bds >= BB * DI * DS) return;
    const int STRIDE = BB * DI * DS;
    float h = 0.f;
    #pragma unroll
    for (int c = 0; c < NC; c++) {
        g_hin[(size_t)c * STRIDE + bds] = h;
        h = fmaf(g_P[(size_t)c * STRIDE + bds], h, g_hl[(size_t)c * STRIDE + bds]);
    }
}

// ---------------- K5c: scan pass3 — scan from h_in, emit gated y (bf16) ---
__global__ void __launch_bounds__(128)
k_scan3(const float* __restrict__ Alog, const float* __restrict__ Dp) {
    int gid = blockIdx.x * 128 + threadIdx.x;
    int grp = gid >> 4;
    int s   = gid & 15;
    int c   = grp / (BB * DI);
    int bd  = grp % (BB * DI);
    int b = bd / DI, d = bd % DI;
    float A   = -__expf(Alog[d*DS + s]);
    float Dpd = Dp[d];
    size_t m0 = (size_t)b * LL + (size_t)c * CL;
    const float* up  = g_u    + m0 * DI + d;
    const float* dtp = g_dt   + m0 * DI + d;
    const float* Bp  = g_xdbc + m0 * NXP + DTR + s;
    const float* Cp  = g_xdbc + m0 * NXP + DTR + DS + s;
    const float* zp  = g_xz   + m0 * (2*DI) + DI + d;
    __nv_bfloat16* yp = g_yg  + m0 * DI + d;
    float h = g_hin[gid];
    #pragma unroll 2
    for (int l = 0; l < CL; l++) {
        float ut  = up [(size_t)l * DI];
        float dtt = dtp[(size_t)l * DI];
        float Bv  = Bp [(size_t)l * NXP];
        float Cv  = Cp [(size_t)l * NXP];
        float dA  = __expf(dtt * A);
        h = fmaf(h, dA, dtt * ut * Bv);
        float pr = h * Cv;
        pr += __shfl_xor_sync(0xffffffffu, pr, 8, 16);
        pr += __shfl_xor_sync(0xffffffffu, pr, 4, 16);
        pr += __shfl_xor_sync(0xffffffffu, pr, 2, 16);
        pr += __shfl_xor_sync(0xffffffffu, pr, 1, 16);
        if (s == 0) {
            float y = pr + ut * Dpd;
            float z = zp[(size_t)l * (2*DI)];
            y *= z / (1.f + __expf(-z));
            yp[(size_t)l * DI] = __float2bfloat16_rn(y);
        }
    }
}

// ---------------- launch ----------------
extern "C" void kernel_launch(void* const* d_in, const int* in_sizes, int n_in,
                              void* d_out, int out_size) {
    const float* x      = (const float*)d_in[0];
    const float* ln_g   = (const float*)d_in[1];
    const float* ln_b   = (const float*)d_in[2];
    const float* W_in   = (const float*)d_in[3];
    const float* conv_w = (const float*)d_in[4];
    const float* conv_b = (const float*)d_in[5];
    const float* W_x    = (const float*)d_in[6];
    const float* W_dt   = (const float*)d_in[7];
    const float* b_dt   = (const float*)d_in[8];
    const float* A_log  = (const float*)d_in[9];
    const float* Dp     = (const float*)d_in[10];
    const float* W_out  = (const float*)d_in[11];
    float* out = (float*)d_out;

    __nv_bfloat16 *p_xn, *p_ub, *p_yg;
    float *p_xz, *p_xdbc;
    cudaGetSymbolAddress((void**)&p_xn,   g_xn);
    cudaGetSymbolAddress((void**)&p_xz,   g_xz);
    cudaGetSymbolAddress((void**)&p_ub,   g_ub);
    cudaGetSymbolAddress((void**)&p_xdbc, g_xdbc);
    cudaGetSymbolAddress((void**)&p_yg,   g_yg);

    {   // layernorm -> bf16 (B,L,C)
        dim3 grid(LL/32, BB), blk(32, 8);
        k_ln<<<grid, blk>>>(x, ln_g, ln_b);
    }
    {   // GEMM1: xz = xn @ W_in   (65536 x 768 x 192)
        dim3 grid((2*DI)/64, MM/128);
        k_bgemm16<CC, false, false><<<grid, 256>>>(p_xn, W_in, p_xz, nullptr, 2*DI, 2*DI);
    }
    {   // conv + silu -> u (fp32) + ub (bf16)
        int n = MM * DI;
        k_conv<<<(n + 255)/256, 256>>>(conv_w, conv_b);
    }
    {   // xdbc = u @ W_x   (N=44 valid, stride 64)
        dim3 grid(1, MM/128);
        k_bgemm16<DI, true, false><<<grid, 256>>>(p_ub, W_x, p_xdbc, nullptr, NX, NXP);
    }
    // dt
    k_dt<<<MM/64, 384>>>(W_dt, b_dt);
    // chunked scan
    k_scan1<<<(NC*BB*DI*DS)/128, 128>>>(A_log);
    k_scan2<<<(BB*DI*DS + 255)/256, 256>>>();
    k_scan3<<<(NC*BB*DI*DS)/128, 128>>>(A_log, Dp);
    {   // GEMM3 fused transpose+residual: out = (yg @ W_out)^T + x
        dim3 grid(CC/64, MM/128);
        k_bgemm16<DI, false, true><<<grid, 256>>>(p_yg, W_out, out, x, CC, 0);
    }
}